// round 12
// baseline (speedup 1.0000x reference)
#include <cuda_runtime.h>
#include <cuda_fp16.h>
#include <math.h>
#include <stdint.h>

// ---------------------------------------------------------------------------
// Problem constants
// ---------------------------------------------------------------------------
#define B_   8
#define C_   128
#define N_   4096
#define EPSN 1e-12f
// exp(x/0.1) = 2^(x * 10*log2(e)); fold sqrt of scale into both vectors.
#define ALPHA 3.7982826f          // sqrt(14.4269504089)

#define TM   128
#define NPAIRS 528                // 32*33/2 upper-triangular 128x128 tiles
#define NU   (B_ * NPAIRS)        // 4224 work units (one tile each)
#define GRIDP 148                 // persistent CTAs

// Scratch: normalized+scaled features fp16, [b][n][c] (8 MB)
__device__ __align__(16) __half g_vh[(size_t)B_ * N_ * C_];
// Per-row partial sums
__device__ float g_pos[B_ * N_];
__device__ float g_tot[B_ * N_];

// ---------------------------------------------------------------------------
// Helpers
// ---------------------------------------------------------------------------
__device__ __forceinline__ uint32_t smem_u32(const void* p) {
    uint32_t a;
    asm("{ .reg .u64 t; cvta.to.shared.u64 t, %1; cvt.u32.u64 %0, t; }"
        : "=r"(a) : "l"(p));
    return a;
}

__device__ __forceinline__ float ex2f(float x) {
    float y;
    asm("ex2.approx.f32 %0, %1;" : "=f"(y) : "f"(x));
    return y;
}

#define LDSM4(R0, R1, R2, R3, ADDR) \
    asm volatile("ldmatrix.sync.aligned.m8n8.x4.shared.b16 {%0,%1,%2,%3}, [%4];" \
                 : "=r"(R0), "=r"(R1), "=r"(R2), "=r"(R3) : "r"(ADDR))

#define MMA16816(AC, A0, A1, A2, A3, Bv0, Bv1) \
    asm volatile("mma.sync.aligned.m16n8k16.row.col.f32.f16.f16.f32 " \
                 "{%0,%1,%2,%3}, {%4,%5,%6,%7}, {%8,%9}, {%0,%1,%2,%3};" \
                 : "+f"((AC)[0]), "+f"((AC)[1]), "+f"((AC)[2]), "+f"((AC)[3]) \
                 : "r"(A0), "r"(A1), "r"(A2), "r"(A3), "r"(Bv0), "r"(Bv1))

#define CP_ASYNC16(DST, SRC) \
    asm volatile("cp.async.cg.shared.global [%0], [%1], 16;" :: "r"(DST), "l"(SRC))
#define CP_COMMIT()  asm volatile("cp.async.commit_group;" ::: "memory")
#define CP_WAIT0()   asm volatile("cp.async.wait_group 0;" ::: "memory")

// ---------------------------------------------------------------------------
// Kernel 1: normalize + scale by ALPHA + transpose -> fp16 [b][n][c].
// Also zeroes g_pos/g_tot rows and the output scalar.
// ---------------------------------------------------------------------------
__global__ void normalize_kernel(const float* __restrict__ feat,
                                 float* __restrict__ out) {
    __shared__ float t[C_][33];
    __shared__ float invn[32];
    const int b = blockIdx.y, n0 = blockIdx.x * 32, tid = threadIdx.x;
    const float* fb = feat + (size_t)b * C_ * N_;

    if (tid < 32) {
        g_pos[b * N_ + n0 + tid] = 0.0f;
        g_tot[b * N_ + n0 + tid] = 0.0f;
    }
    if (b == 0 && n0 == 0 && tid == 32) out[0] = 0.0f;

    for (int idx = tid; idx < C_ * 32; idx += 256) {
        int c = idx >> 5, nl = idx & 31;
        t[c][nl] = fb[(size_t)c * N_ + n0 + nl];
    }
    __syncthreads();

    const int w = tid >> 5, lane = tid & 31;
    #pragma unroll
    for (int p = 0; p < 4; p++) {
        int nl = w * 4 + p;
        float v0 = t[lane][nl], v1 = t[lane + 32][nl];
        float v2 = t[lane + 64][nl], v3 = t[lane + 96][nl];
        float s = v0 * v0 + v1 * v1 + v2 * v2 + v3 * v3;
        #pragma unroll
        for (int o = 16; o > 0; o >>= 1) s += __shfl_xor_sync(0xffffffffu, s, o);
        if (lane == 0) invn[nl] = ALPHA / fmaxf(sqrtf(s), EPSN);
    }
    __syncthreads();

    __half* vb = g_vh + ((size_t)b * N_ + n0) * C_;
    for (int idx = tid; idx < 32 * C_; idx += 256) {
        int nl = idx >> 7, c = idx & 127;
        vb[(size_t)nl * C_ + c] = __float2half(t[c][nl] * invn[nl]);
    }
}

// ---------------------------------------------------------------------------
// Tile copy: 128 rows x 256B (fp16) global -> swizzled smem via cp.async.
// Swizzle: physical 16B-chunk = c ^ (row & 7)
// ---------------------------------------------------------------------------
__device__ __forceinline__ void cp_tile(uint32_t sbase,
                                        const __half* __restrict__ src,
                                        int tid) {
    #pragma unroll
    for (int it = 0; it < 8; it++) {
        int idx = tid + it * 256;
        int r = idx >> 4, c = idx & 15;
        uint32_t dst = sbase + (uint32_t)r * 256u + (uint32_t)((c ^ (r & 7)) << 4);
        const char* g = (const char*)src + (size_t)r * 256 + c * 16;
        CP_ASYNC16(dst, g);
    }
}

// ---------------------------------------------------------------------------
// Half-tile K-loop: 32 rows x 32 cols x K=128 -> acc[2][4][4].
// ---------------------------------------------------------------------------
__device__ __forceinline__ void khalf(float (&acc)[2][4][4],
                                      const uint32_t (&af)[2][8][4],
                                      uint32_t sB,
                                      uint32_t bRow0, int bR70,
                                      uint32_t bRow1, int bR71, int csB) {
    #pragma unroll
    for (int mt = 0; mt < 2; mt++)
        #pragma unroll
        for (int nt = 0; nt < 4; nt++)
            #pragma unroll
            for (int q = 0; q < 4; q++) acc[mt][nt][q] = 0.0f;

    #pragma unroll
    for (int k = 0; k < 8; k++) {
        uint32_t bf0[4], bf1[4];
        LDSM4(bf0[0], bf0[1], bf0[2], bf0[3],
              sB + bRow0 + (uint32_t)(((2 * k + csB) ^ bR70) << 4));
        LDSM4(bf1[0], bf1[1], bf1[2], bf1[3],
              sB + bRow1 + (uint32_t)(((2 * k + csB) ^ bR71) << 4));
        #pragma unroll
        for (int mt = 0; mt < 2; mt++) {
            MMA16816(acc[mt][0], af[mt][k][0], af[mt][k][1], af[mt][k][2],
                     af[mt][k][3], bf0[0], bf0[1]);
            MMA16816(acc[mt][1], af[mt][k][0], af[mt][k][1], af[mt][k][2],
                     af[mt][k][3], bf0[2], bf0[3]);
            MMA16816(acc[mt][2], af[mt][k][0], af[mt][k][1], af[mt][k][2],
                     af[mt][k][3], bf1[0], bf1[1]);
            MMA16816(acc[mt][3], af[mt][k][0], af[mt][k][1], af[mt][k][2],
                     af[mt][k][3], bf1[2], bf1[3]);
        }
    }
}

// ---------------------------------------------------------------------------
// Epilogue, off-diagonal tile (rt < ct): rows AND columns credited.
// ---------------------------------------------------------------------------
__device__ __forceinline__ void epi_off(const float (&acc)[2][4][4], int h,
                                        const unsigned* __restrict__ cmask,
                                        const int (&labr)[2][2],
                                        int warpN, int lane,
                                        float (&pos)[4], float (&tot)[4],
                                        float* __restrict__ colP_s,
                                        float* __restrict__ colT_s) {
    const int coff = warpN + h * 32;
    const int lw = coff >> 5;
    float colT[4][2], colP[4][2];
    #pragma unroll
    for (int n = 0; n < 4; n++) {
        colT[n][0] = colT[n][1] = 0.f;
        colP[n][0] = colP[n][1] = 0.f;
    }
    #pragma unroll
    for (int mt = 0; mt < 2; mt++) {
        const unsigned w0 = cmask[labr[mt][0] * 4 + lw];
        const unsigned w1 = cmask[labr[mt][1] * 4 + lw];
        float t0 = 0.f, t1 = 0.f, p0 = 0.f, p1 = 0.f;
        #pragma unroll
        for (int ntl = 0; ntl < 4; ntl++) {
            const int sh = ntl * 8 + 2 * (lane & 3);
            const unsigned b0 = w0 >> sh;
            const unsigned b1 = w1 >> sh;
            float e00 = ex2f(acc[mt][ntl][0]);
            float e01 = ex2f(acc[mt][ntl][1]);
            float e10 = ex2f(acc[mt][ntl][2]);
            float e11 = ex2f(acc[mt][ntl][3]);
            float m00 = (b0 & 1u) ? e00 : 0.f;
            float m01 = (b0 & 2u) ? e01 : 0.f;
            float m10 = (b1 & 1u) ? e10 : 0.f;
            float m11 = (b1 & 2u) ? e11 : 0.f;
            t0 += e00 + e01;  t1 += e10 + e11;
            p0 += m00 + m01;  p1 += m10 + m11;
            colT[ntl][0] += e00 + e10;  colT[ntl][1] += e01 + e11;
            colP[ntl][0] += m00 + m10;  colP[ntl][1] += m01 + m11;
        }
        tot[mt * 2 + 0] += t0;  tot[mt * 2 + 1] += t1;
        pos[mt * 2 + 0] += p0;  pos[mt * 2 + 1] += p1;
    }
    // column reduce over the 8 row-lane-groups (lane bits 2,3,4)
    #pragma unroll
    for (int ntl = 0; ntl < 4; ntl++) {
        #pragma unroll
        for (int par = 0; par < 2; par++) {
            float vT = colT[ntl][par], vP = colP[ntl][par];
            vT += __shfl_xor_sync(0xffffffffu, vT, 4);
            vT += __shfl_xor_sync(0xffffffffu, vT, 8);
            vT += __shfl_xor_sync(0xffffffffu, vT, 16);
            vP += __shfl_xor_sync(0xffffffffu, vP, 4);
            vP += __shfl_xor_sync(0xffffffffu, vP, 8);
            vP += __shfl_xor_sync(0xffffffffu, vP, 16);
            if (lane < 4) {
                int c = coff + ntl * 8 + 2 * lane + par;
                atomicAdd(&colT_s[c], vT);
                atomicAdd(&colP_s[c], vP);
            }
        }
    }
}

// ---------------------------------------------------------------------------
// Epilogue, diagonal tile (rt == ct): rows only, zero the diagonal.
// ---------------------------------------------------------------------------
__device__ __forceinline__ void epi_diag(const float (&acc)[2][4][4], int h,
                                         const unsigned* __restrict__ cmask,
                                         const int (&labr)[2][2],
                                         const int (&growb)[2],
                                         int warpN, int lane, int ct,
                                         float (&pos)[4], float (&tot)[4]) {
    const int coff = warpN + h * 32;
    const int lw = coff >> 5;
    const int cb = ct * TM + coff;
    #pragma unroll
    for (int mt = 0; mt < 2; mt++) {
        const unsigned w0 = cmask[labr[mt][0] * 4 + lw];
        const unsigned w1 = cmask[labr[mt][1] * 4 + lw];
        const int g0 = growb[mt], g1 = growb[mt] + 8;
        float t0 = 0.f, t1 = 0.f, p0 = 0.f, p1 = 0.f;
        #pragma unroll
        for (int ntl = 0; ntl < 4; ntl++) {
            const int sh = ntl * 8 + 2 * (lane & 3);
            const unsigned b0 = w0 >> sh;
            const unsigned b1 = w1 >> sh;
            float e00 = ex2f(acc[mt][ntl][0]);
            float e01 = ex2f(acc[mt][ntl][1]);
            float e10 = ex2f(acc[mt][ntl][2]);
            float e11 = ex2f(acc[mt][ntl][3]);
            const int gc = cb + ntl * 8 + 2 * (lane & 3);
            if (g0 == gc)     e00 = 0.f;
            if (g0 == gc + 1) e01 = 0.f;
            if (g1 == gc)     e10 = 0.f;
            if (g1 == gc + 1) e11 = 0.f;
            t0 += e00 + e01;
            t1 += e10 + e11;
            p0 += ((b0 & 1u) ? e00 : 0.f) + ((b0 & 2u) ? e01 : 0.f);
            p1 += ((b1 & 1u) ? e10 : 0.f) + ((b1 & 2u) ? e11 : 0.f);
        }
        tot[mt * 2 + 0] += t0;  tot[mt * 2 + 1] += t1;
        pos[mt * 2 + 0] += p0;  pos[mt * 2 + 1] += p1;
    }
}

// ---------------------------------------------------------------------------
// Unit decode: u -> (b, rt, ct), upper triangle incl. diagonal.
// ---------------------------------------------------------------------------
__device__ __forceinline__ void decode_u(int u, int& b, int& rt, int& ct) {
    b = u / NPAIRS;
    int p = u - b * NPAIRS;
    int r = 0;
    while (p >= 32 - r) { p -= 32 - r; r++; }
    rt = r;
    ct = r + p;
}

// ---------------------------------------------------------------------------
// Kernel 2: persistent symmetric HMMA GEMM + fused epilogue.
// One unit = one 128x128 tile (rt, ct) of one batch, ct >= rt.
// Dyn smem: A0 32K | A1 32K | B0 32K | B1 32K | cmask 256B | colP/colT 1K
//           | posS/totS 2K  = ~134.4 KB
// ---------------------------------------------------------------------------
#define SM_A1    32768
#define SM_B0    65536
#define SM_B1    98304
#define SM_CMASK 131072
#define SM_COLP  (SM_CMASK + 256)
#define SM_COLT  (SM_COLP + 512)
#define SM_POSS  (SM_COLT + 512)
#define SM_TOTS  (SM_POSS + 1024)
#define SM_DYN   (SM_TOTS + 1024)

__global__ void __launch_bounds__(256, 1)
loss_kernel(const int* __restrict__ labels) {
    extern __shared__ char sm[];
    const int tid = threadIdx.x, wid = tid >> 5, lane = tid & 31;

    unsigned* cmask = (unsigned*)(sm + SM_CMASK);   // [16 classes][4 words]
    float* colP_s = (float*)(sm + SM_COLP);         // [128]
    float* colT_s = (float*)(sm + SM_COLT);         // [128]
    float* posS   = (float*)(sm + SM_POSS);         // [128][2]
    float* totS   = (float*)(sm + SM_TOTS);

    const uint32_t sAb[2] = { smem_u32(sm), smem_u32(sm + SM_A1) };
    const uint32_t sBb[2] = { smem_u32(sm + SM_B0), smem_u32(sm + SM_B1) };

    const int warpM = (wid & 3) * 32;
    const int warpN = (wid >> 2) * 64;

    // ldmatrix per-lane address components
    const int rA  = warpM + (lane & 15);
    const int csA = lane >> 4;
    const int rBl = (lane & 7) + ((lane & 16) >> 1);
    const int csB = (lane >> 3) & 1;

    uint32_t bRow[4];
    int bR7[4];
    #pragma unroll
    for (int np = 0; np < 4; np++) {
        int row = warpN + np * 16 + rBl;
        bRow[np] = (uint32_t)row * 256u;
        bR7[np] = row & 7;
    }

    int u = blockIdx.x;
    int pb = 0;
    if (u < NU) {   // prologue: load first unit's tiles
        int b, rt, ct;
        decode_u(u, b, rt, ct);
        const __half* vb = g_vh + (size_t)b * N_ * C_;
        cp_tile(sAb[0], vb + (size_t)(rt * TM) * C_, tid);
        cp_tile(sBb[0], vb + (size_t)(ct * TM) * C_, tid);
        CP_COMMIT();
    }

    while (u < NU) {
        int b, rt, ct;
        decode_u(u, b, rt, ct);
        const int un = u + gridDim.x;
        const int* lb = labels + b * N_;

        CP_WAIT0();
        __syncthreads();    // tiles ready; prev unit's flush complete

        // zero column accumulators
        if (tid < 128) { colP_s[tid] = 0.0f; colT_s[tid] = 0.0f; }

        // per-class column bitmasks for the ct tile (4 words per class)
        if (wid < 4) {
            int lab = lb[ct * TM + wid * 32 + lane];
            #pragma unroll
            for (int c = 0; c < 16; c++) {
                unsigned m = __ballot_sync(0xffffffffu, lab == c);
                if (lane == c) cmask[c * 4 + wid] = m;
            }
        }

        // prefetch next unit's tiles into the other buffers
        if (un < NU) {
            int bn, rtn, ctn;
            decode_u(un, bn, rtn, ctn);
            const __half* vbn = g_vh + (size_t)bn * N_ * C_;
            cp_tile(sAb[pb ^ 1], vbn + (size_t)(rtn * TM) * C_, tid);
            cp_tile(sBb[pb ^ 1], vbn + (size_t)(ctn * TM) * C_, tid);
            CP_COMMIT();
        }

        // row identities
        int growb[2], labr[2][2];
        #pragma unroll
        for (int mt = 0; mt < 2; mt++) {
            growb[mt] = rt * TM + warpM + mt * 16 + (lane >> 2);
            labr[mt][0] = lb[growb[mt]];
            labr[mt][1] = lb[growb[mt] + 8];
        }

        // A fragments for this tile
        uint32_t af[2][8][4];
        #pragma unroll
        for (int mt = 0; mt < 2; mt++) {
            int row = rA + mt * 16;
            uint32_t base = sAb[pb] + (uint32_t)row * 256u;
            int r7 = row & 7;
            #pragma unroll
            for (int k = 0; k < 8; k++) {
                uint32_t addr = base + (uint32_t)(((2 * k + csA) ^ r7) << 4);
                LDSM4(af[mt][k][0], af[mt][k][1], af[mt][k][2], af[mt][k][3],
                      addr);
            }
        }
        __syncthreads();    // cmask + col-zero visible

        float pos[4] = {0.f, 0.f, 0.f, 0.f};
        float tot[4] = {0.f, 0.f, 0.f, 0.f};
        float acc0[2][4][4], acc1[2][4][4];

        const uint32_t sB = sBb[pb];
        khalf(acc0, af, sB, bRow[0], bR7[0], bRow[1], bR7[1], csB);
        khalf(acc1, af, sB, bRow[2], bR7[2], bRow[3], bR7[3], csB);

        if (rt == ct) {
            epi_diag(acc0, 0, cmask, labr, growb, warpN, lane, ct, pos, tot);
            epi_diag(acc1, 1, cmask, labr, growb, warpN, lane, ct, pos, tot);
        } else {
            epi_off(acc0, 0, cmask, labr, warpN, lane, pos, tot,
                    colP_s, colT_s);
            epi_off(acc1, 1, cmask, labr, warpN, lane, pos, tot,
                    colP_s, colT_s);
        }

        // row merge: reduce 4 lanes per row, merge 2 N-warps via smem
        #pragma unroll
        for (int q = 0; q < 4; q++) {
            pos[q] += __shfl_xor_sync(0xffffffffu, pos[q], 1);
            pos[q] += __shfl_xor_sync(0xffffffffu, pos[q], 2);
            tot[q] += __shfl_xor_sync(0xffffffffu, tot[q], 1);
            tot[q] += __shfl_xor_sync(0xffffffffu, tot[q], 2);
        }
        const int widN = wid >> 2;
        if ((lane & 3) == 0) {
            #pragma unroll
            for (int mt = 0; mt < 2; mt++) {
                int rl = warpM + mt * 16 + (lane >> 2);
                posS[rl * 2 + widN]       = pos[mt * 2 + 0];
                totS[rl * 2 + widN]       = tot[mt * 2 + 0];
                posS[(rl + 8) * 2 + widN] = pos[mt * 2 + 1];
                totS[(rl + 8) * 2 + widN] = tot[mt * 2 + 1];
            }
        }
        __syncthreads();

        // flush: rows always; columns only for off-diagonal tiles
        if (tid < TM) {
            float P = posS[tid * 2] + posS[tid * 2 + 1];
            float T = totS[tid * 2] + totS[tid * 2 + 1];
            atomicAdd(&g_pos[b * N_ + rt * TM + tid], P);
            atomicAdd(&g_tot[b * N_ + rt * TM + tid], T);
            if (rt != ct) {
                atomicAdd(&g_pos[b * N_ + ct * TM + tid], colP_s[tid]);
                atomicAdd(&g_tot[b * N_ + ct * TM + tid], colT_s[tid]);
            }
        }

        u = un;
        pb ^= 1;
    }
}

// ---------------------------------------------------------------------------
// Kernel 3: finalize — dev = log(T) - log(P) per row, mean into out.
// ---------------------------------------------------------------------------
__global__ void finalize_kernel(float* __restrict__ out) {
    __shared__ float ws[8];
    const int idx = blockIdx.x * 256 + threadIdx.x;
    const int lane = threadIdx.x & 31, wid = threadIdx.x >> 5;
    float dev = __logf(g_tot[idx]) - __logf(g_pos[idx]);
    #pragma unroll
    for (int o = 16; o > 0; o >>= 1) dev += __shfl_xor_sync(0xffffffffu, dev, o);
    if (lane == 0) ws[wid] = dev;
    __syncthreads();
    if (threadIdx.x == 0) {
        float s = 0.0f;
        #pragma unroll
        for (int w = 0; w < 8; w++) s += ws[w];
        atomicAdd(out, s * (1.0f / ((float)B_ * (float)N_)));
    }
}

// ---------------------------------------------------------------------------
// Launch
// ---------------------------------------------------------------------------
extern "C" void kernel_launch(void* const* d_in, const int* in_sizes, int n_in,
                              void* d_out, int out_size) {
    const float* feat   = (const float*)d_in[0];
    const int*   labels = (const int*)d_in[1];
    float*       out    = (float*)d_out;

    dim3 gn(N_ / 32, B_);
    normalize_kernel<<<gn, 256>>>(feat, out);

    cudaFuncSetAttribute(loss_kernel,
                         cudaFuncAttributeMaxDynamicSharedMemorySize, SM_DYN);
    loss_kernel<<<GRIDP, 256, SM_DYN>>>(labels);

    finalize_kernel<<<(B_ * N_) / 256, 256>>>(out);
}